// round 16
// baseline (speedup 1.0000x reference)
#include <cuda_runtime.h>
#include <cuda_bf16.h>
#include <cstdint>

// CapsNet dynamic routing. u_hat never materialized; bf16 hi/lo 3-pass GEMMs
// on mma.sync (m16n8k16, fp32 accum). Pre-swizzled operands + cp.async.bulk.
// 512-thread GEMM CTAs (16 warps); fragment-level software pipeline (ping-
// pong register buffers) + ldsm4 B loads.
// Launches (4): conv+Wc(0) | gemm_s(0)+squash | fused(1) | fused(2)
// fused(t) = [M-GEMM(t-1) + b-update + Wc(t)] --chunk flags--> [s-GEMM(t)+squash]
//   inp: [256,1152,8] fp32, W: [1152,10,16,8] fp32, out v: [256,10,16] fp32
//
// All __device__ globals referenced only inside device code (host-passed
// __device__ symbols silently resolve to ATS host memory on GB300).

#define BATCH   256
#define INCH    1152
#define INU     8
#define OUTCH   10
#define OUTU    16
#define KDIM    (INCH*INU)     // 9216
#define NDIM    (OUTCH*OUTU)   // 160
#define NCHUNK  144            // 64-k chunks (8 capsules each)
#define SPLITS_S 36            // s-GEMM K splits (4 chunks = 256 K per CTA)

// ---------------- device globals (pre-swizzled tile storage) ---------------
__device__ __align__(16) unsigned char g_A_hi[NCHUNK * 4 * 8192];   // [chunk][mblk][64x128B]
__device__ __align__(16) unsigned char g_A_lo[NCHUNK * 4 * 8192];
__device__ __align__(16) unsigned char g_AT_hi[4 * NCHUNK * 8192];  // [kc][ikblk][64x128B]
__device__ __align__(16) unsigned char g_AT_lo[4 * NCHUNK * 8192];
__device__ __align__(16) unsigned char g_Bt_hi[NCHUNK * 20480];     // [chunk][160x128B]
__device__ __align__(16) unsigned char g_Bt_lo[NCHUNK * 20480];
__device__ __align__(16) unsigned char g_vT2_hi[4 * 20480];         // [kc][160x128B]
__device__ __align__(16) unsigned char g_vT2_lo[4 * 20480];
__device__ float g_part_s[SPLITS_S * BATCH * NDIM];                 // 5.9 MB
__device__ float g_b[INCH * OUTCH];
__device__ int   g_cnt[4];                                          // per-Mtile arrivals
__device__ int   g_flag[NCHUNK];                                    // Bt chunk ready

__device__ __forceinline__ uint32_t smem_to_u32(const void* p) {
    uint32_t a;
    asm("{ .reg .u64 t; cvta.to.shared.u64 t, %1; cvt.u32.u64 %0, t; }"
        : "=r"(a) : "l"(p));
    return a;
}
__device__ __forceinline__ void split_bf16(float x, __nv_bfloat16& h, __nv_bfloat16& l) {
    h = __float2bfloat16(x);
    l = __float2bfloat16(x - __bfloat162float(h));
}
__device__ __forceinline__ void ldsm4(uint32_t& r0, uint32_t& r1, uint32_t& r2,
                                      uint32_t& r3, uint32_t addr) {
    asm volatile("ldmatrix.sync.aligned.m8n8.x4.shared.b16 {%0,%1,%2,%3}, [%4];"
                 : "=r"(r0), "=r"(r1), "=r"(r2), "=r"(r3) : "r"(addr));
}
__device__ __forceinline__ void ldsm2(uint32_t& r0, uint32_t& r1, uint32_t addr) {
    asm volatile("ldmatrix.sync.aligned.m8n8.x2.shared.b16 {%0,%1}, [%2];"
                 : "=r"(r0), "=r"(r1) : "r"(addr));
}
__device__ __forceinline__ void mma16816(float* d, const uint32_t* a,
                                         const uint32_t* b) {
    asm volatile(
        "mma.sync.aligned.m16n8k16.row.col.f32.bf16.bf16.f32 "
        "{%0,%1,%2,%3}, {%4,%5,%6,%7}, {%8,%9}, {%0,%1,%2,%3};"
        : "+f"(d[0]), "+f"(d[1]), "+f"(d[2]), "+f"(d[3])
        : "r"(a[0]), "r"(a[1]), "r"(a[2]), "r"(a[3]), "r"(b[0]), "r"(b[1]));
}

// ---- mbarrier + bulk-copy primitives (sm_90 baseline PTX) ----
#define MBAR_INIT(a, c) \
    asm volatile("mbarrier.init.shared.b64 [%0], %1;" \
                 :: "r"((uint32_t)(a)), "r"((uint32_t)(c)) : "memory")
#define MBAR_EXPECT(a, tx) \
    asm volatile("mbarrier.arrive.expect_tx.shared.b64 _, [%0], %1;" \
                 :: "r"((uint32_t)(a)), "r"((uint32_t)(tx)) : "memory")
#define MBAR_WAIT(a, ph) do { \
    uint32_t _mb = (uint32_t)(a); uint32_t _p = (uint32_t)(ph); uint32_t _d; \
    asm volatile("{\n\t.reg .pred p;\n\t" \
        "mbarrier.try_wait.parity.acquire.cta.shared::cta.b64 p, [%1], %2;\n\t" \
        "selp.b32 %0, 1, 0, p;\n\t}" : "=r"(_d) : "r"(_mb), "r"(_p) : "memory"); \
    if (!_d) { \
        asm volatile("{\n\t.reg .pred P1;\n\tWL_%=:\n\t" \
            "mbarrier.try_wait.parity.acquire.cta.shared::cta.b64 P1, [%0], %1, 0x989680;\n\t" \
            "@P1 bra.uni WD_%=;\n\tbra.uni WL_%=;\n\tWD_%=:\n\t}" \
            :: "r"(_mb), "r"(_p) : "memory"); \
    } } while (0)
__device__ __forceinline__ void bulkcp(uint32_t dst, const void* src,
                                       uint32_t bytes, uint32_t mbar) {
    asm volatile(
        "cp.async.bulk.shared::cluster.global.mbarrier::complete_tx::bytes "
        "[%0], [%1], %2, [%3];"
        :: "r"(dst), "l"(src), "r"(bytes), "r"(mbar) : "memory");
}

// ---------------------------------------------------------------------------
// Wc body: g_Bt[chunk] (pre-swizzled 160x128B) = c[i,o]*W[i,o,u,k] hi/lo.
// ---------------------------------------------------------------------------
template <int NT>
__device__ __forceinline__ void wc_body(const float* __restrict__ W, int chunk,
                                        const float (*c_s)[10], int tid) {
    const float4* W4 = (const float4*)(W + (size_t)chunk * 8 * 1280);
    unsigned char* bh = g_Bt_hi + (size_t)chunk * 20480;
    unsigned char* bl = g_Bt_lo + (size_t)chunk * 20480;
    #pragma unroll
    for (int r = 0; r < 2560 / NT; r++) {
        int q = tid + r * NT;                // 0..2559 float4s (8 caps x 320)
        int i_off = q / 320;
        int rem = q - i_off * 320;
        int o = rem >> 5;
        int rem2 = rem & 31;
        int u = rem2 >> 1, kh = rem2 & 1;
        float4 f = W4[q];
        float cv = c_s[i_off][o];
        __nv_bfloat16 h0,l0,h1,l1,h2,l2,h3,l3;
        split_bf16(f.x * cv, h0, l0);
        split_bf16(f.y * cv, h1, l1);
        split_bf16(f.z * cv, h2, l2);
        split_bf16(f.w * cv, h3, l3);
        uint2 ph, pl;
        ph.x = (uint32_t)__bfloat16_as_ushort(h0) | ((uint32_t)__bfloat16_as_ushort(h1) << 16);
        ph.y = (uint32_t)__bfloat16_as_ushort(h2) | ((uint32_t)__bfloat16_as_ushort(h3) << 16);
        pl.x = (uint32_t)__bfloat16_as_ushort(l0) | ((uint32_t)__bfloat16_as_ushort(l1) << 16);
        pl.y = (uint32_t)__bfloat16_as_ushort(l2) | ((uint32_t)__bfloat16_as_ushort(l3) << 16);
        int row = o * 16 + u;
        uint32_t off = (uint32_t)row * 128 + ((i_off ^ (row & 7)) << 4) + kh * 8;
        *(uint2*)(bh + off) = ph;
        *(uint2*)(bl + off) = pl;
    }
}

// ---------------------------------------------------------------------------
// One-time: inp -> bf16 hi/lo pre-swizzled tiles (both layouts); fused Wc(0);
// resets g_cnt and g_flag. grid (144, 4), 256 threads.
// ---------------------------------------------------------------------------
__global__ void conv_inp(const float* __restrict__ inp, const float* __restrict__ W) {
    __shared__ unsigned short sh_hi[64][72];
    __shared__ unsigned short sh_lo[64][72];
    __shared__ float c_s[8][10];
    int ik0 = blockIdx.x * 64, b0 = blockIdx.y * 64;
    int tid = threadIdx.x;

    if (blockIdx.y == 1 && tid == 0) g_flag[blockIdx.x] = 0;
    if (blockIdx.x == 0 && blockIdx.y == 0 && tid < 4) g_cnt[tid] = 0;

    #pragma unroll
    for (int it = 0; it < 16; it++) {
        int row = it * 4 + (tid >> 6);
        int col = tid & 63;
        float x = inp[(size_t)(b0 + row) * KDIM + ik0 + col];
        __nv_bfloat16 h, l;
        split_bf16(x, h, l);
        sh_hi[row][col] = __bfloat16_as_ushort(h);
        sh_lo[row][col] = __bfloat16_as_ushort(l);
    }
    __syncthreads();

    unsigned char* Ah = g_A_hi + ((size_t)blockIdx.x * 4 + blockIdx.y) * 8192;
    unsigned char* Al = g_A_lo + ((size_t)blockIdx.x * 4 + blockIdx.y) * 8192;
    unsigned char* Th = g_AT_hi + ((size_t)blockIdx.y * NCHUNK + blockIdx.x) * 8192;
    unsigned char* Tl = g_AT_lo + ((size_t)blockIdx.y * NCHUNK + blockIdx.x) * 8192;

    #pragma unroll
    for (int k = 0; k < 4; k++) {
        int w = tid + (k << 8);
        int r = w >> 4, g = w & 15;
        uint32_t off = (uint32_t)r * 128 + ((((g >> 1) ^ (r & 7))) << 4) + (g & 1) * 8;
        {
            int c0 = g * 4;
            uint2 vh, vl;
            vh.x = (uint32_t)sh_hi[r][c0] | ((uint32_t)sh_hi[r][c0+1] << 16);
            vh.y = (uint32_t)sh_hi[r][c0+2] | ((uint32_t)sh_hi[r][c0+3] << 16);
            vl.x = (uint32_t)sh_lo[r][c0] | ((uint32_t)sh_lo[r][c0+1] << 16);
            vl.y = (uint32_t)sh_lo[r][c0+2] | ((uint32_t)sh_lo[r][c0+3] << 16);
            *(uint2*)(Ah + off) = vh;
            *(uint2*)(Al + off) = vl;
        }
        {
            int c0 = g * 4;
            uint2 vh, vl;
            vh.x = (uint32_t)sh_hi[c0][r] | ((uint32_t)sh_hi[c0+1][r] << 16);
            vh.y = (uint32_t)sh_hi[c0+2][r] | ((uint32_t)sh_hi[c0+3][r] << 16);
            vl.x = (uint32_t)sh_lo[c0][r] | ((uint32_t)sh_lo[c0+1][r] << 16);
            vl.y = (uint32_t)sh_lo[c0+2][r] | ((uint32_t)sh_lo[c0+3][r] << 16);
            *(uint2*)(Th + off) = vh;
            *(uint2*)(Tl + off) = vl;
        }
    }

    if (blockIdx.y == 0) {
        if (tid < 80) c_s[tid / 10][tid % 10] = 0.1f;
        __syncthreads();
        wc_body<256>(W, blockIdx.x, c_s, tid);
    }
}

// ---------------------------------------------------------------------------
// Per-chunk staging (4 x 56 KB): chunk c at c*57344:
//   AH @0 (8192) | AL @8192 | BH @16384 (20480) | BL @36864
// M_s (phase-1 epilogue, 40960 B) lives at 188416 = chunk3's B region.
// GEMM: 512 thr, 16 warps (4M x 4N), warp tile 16x40, acc 20 regs,
// ping-pong fragment pipeline, ldsm4 B loads.
// ---------------------------------------------------------------------------
#define CHB 57344
#define SG_TOT (4*CHB)      // 229376
#define MS_OFF (3*CHB + 16384)

__device__ __forceinline__ uint32_t swz(uint32_t base, int row, int col16) {
    return base + (uint32_t)row * 128 + (uint32_t)((col16 ^ (row & 7)) << 4);
}

__device__ __forceinline__ void gemm_mainloop(
    uint32_t sb, uint32_t mb0, float (*acc)[4],
    int warp_m, int warp_n, int lane) {
    int a_row_l  = ((lane >> 3) & 1) * 8 + (lane & 7);
    int a_c16_l  = lane >> 4;
    int b2_row_l = lane & 7;                            // ldsm2 rows
    int b4_row_l = ((lane >> 4) & 1) * 8 + (lane & 7);  // ldsm4: 2nd pair +8
    int b_c16_l  = (lane >> 3) & 1;

    uint32_t ah[2][4], al[2][4], bh[2][5][2], bl[2][5][2];

    auto load = [&](int buf, int c, int ks) {
        uint32_t cb = sb + c * CHB;
        int arow = warp_m * 16 + a_row_l;
        int ac = (ks << 1) | a_c16_l;
        ldsm4(ah[buf][0], ah[buf][1], ah[buf][2], ah[buf][3], swz(cb + 0, arow, ac));
        ldsm4(al[buf][0], al[buf][1], al[buf][2], al[buf][3], swz(cb + 8192, arow, ac));
        int bc = (ks << 1) | b_c16_l;
        #pragma unroll
        for (int pp = 0; pp < 2; pp++) {
            int brow = warp_n * 40 + pp * 16 + b4_row_l;
            ldsm4(bh[buf][2*pp][0], bh[buf][2*pp][1], bh[buf][2*pp+1][0], bh[buf][2*pp+1][1],
                  swz(cb + 16384, brow, bc));
            ldsm4(bl[buf][2*pp][0], bl[buf][2*pp][1], bl[buf][2*pp+1][0], bl[buf][2*pp+1][1],
                  swz(cb + 36864, brow, bc));
        }
        {
            int brow = warp_n * 40 + 32 + b2_row_l;
            ldsm2(bh[buf][4][0], bh[buf][4][1], swz(cb + 16384, brow, bc));
            ldsm2(bl[buf][4][0], bl[buf][4][1], swz(cb + 36864, brow, bc));
        }
    };

    MBAR_WAIT(mb0 + 0, 0);
    load(0, 0, 0);
    #pragma unroll
    for (int it = 0; it < 16; it++) {
        int cur = it & 1;
        if (it + 1 < 16) {
            int nc = (it + 1) >> 2, nks = (it + 1) & 3;
            if (nks == 0) MBAR_WAIT(mb0 + nc * 8, 0);
            load(cur ^ 1, nc, nks);
        }
        #pragma unroll
        for (int p = 0; p < 5; p++) {
            mma16816(acc[p], ah[cur], bh[cur][p]);
            mma16816(acc[p], ah[cur], bl[cur][p]);
            mma16816(acc[p], al[cur], bh[cur][p]);
        }
    }
}

// s-GEMM epilogue: write partials, rendezvous, fused squash.
__device__ __forceinline__ void sgemm_epilogue(
    float (*acc)[4], float* __restrict__ out, int t,
    int bx, int by, int tid, int lane, int warp_m, int warp_n) {
    float* po = g_part_s + (size_t)by * (BATCH * NDIM);
    int r_l = lane >> 2, c_l = (lane & 3) * 2;
    int row = bx * 64 + warp_m * 16 + r_l;
    #pragma unroll
    for (int p = 0; p < 5; p++) {
        int col = warp_n * 40 + p * 8 + c_l;
        *(float2*)(po + (size_t)row * NDIM + col) = make_float2(acc[p][0], acc[p][1]);
        *(float2*)(po + (size_t)(row + 8) * NDIM + col) = make_float2(acc[p][2], acc[p][3]);
    }

    __threadfence();
    __syncthreads();
    if (tid == 0) {
        atomicAdd(&g_cnt[bx], 1);
        int tgt = SPLITS_S * (t + 1);
        while (atomicAdd(&g_cnt[bx], 0) < tgt) __nanosleep(20);
    }
    __syncthreads();

    int n  = (by < 28) ? 18 : 17;
    int g0 = (by < 28) ? by * 18 : 28 * 18 + (by - 28) * 17;
    int gl = tid >> 4;
    int u  = tid & 15;
    bool act = gl < n;
    int idx = bx * 10240 + (g0 + gl) * 16 + u;
    float s = 0.f;
    if (act) {
        float a0 = 0.f, a1 = 0.f, a2 = 0.f, a3 = 0.f;
        #pragma unroll
        for (int sp = 0; sp < SPLITS_S; sp += 4) {
            a0 += __ldcg(&g_part_s[(size_t)(sp + 0) * (BATCH * NDIM) + idx]);
            a1 += __ldcg(&g_part_s[(size_t)(sp + 1) * (BATCH * NDIM) + idx]);
            a2 += __ldcg(&g_part_s[(size_t)(sp + 2) * (BATCH * NDIM) + idx]);
            a3 += __ldcg(&g_part_s[(size_t)(sp + 3) * (BATCH * NDIM) + idx]);
        }
        s = (a0 + a1) + (a2 + a3);
    }
    float sq = s * s;
    sq += __shfl_xor_sync(0xffffffffu, sq, 8);
    sq += __shfl_xor_sync(0xffffffffu, sq, 4);
    sq += __shfl_xor_sync(0xffffffffu, sq, 2);
    sq += __shfl_xor_sync(0xffffffffu, sq, 1);
    if (act) {
        float scale = sq / ((1.0f + sq) * sqrtf(sq + 1e-9f));
        float v = s * scale;
        if (t == 2) {
            out[idx] = v;
        } else {
            int b = idx / NDIM;
            int ou = idx - b * NDIM;
            int col = b & 63;
            uint32_t off = (uint32_t)bx * 20480 + ou * 128
                         + (((col >> 3) ^ (ou & 7)) << 4) + (col & 7) * 2;
            __nv_bfloat16 h, l;
            split_bf16(v, h, l);
            *(unsigned short*)(g_vT2_hi + off) = __bfloat16_as_ushort(h);
            *(unsigned short*)(g_vT2_lo + off) = __bfloat16_as_ushort(l);
        }
    }
}

// ---------------------------------------------------------------------------
// Standalone s-GEMM(0) + squash. grid (4, 36), 512 threads.
// ---------------------------------------------------------------------------
__global__ void __launch_bounds__(512, 1)
gemm_s0(float* __restrict__ out) {
    extern __shared__ char sm[];
    __shared__ __align__(8) uint64_t mbar[4];
    uint32_t sb = smem_to_u32(sm);
    uint32_t mb0 = smem_to_u32(mbar);
    int tid = threadIdx.x, lane = tid & 31, wid = tid >> 5;
    int warp_m = wid & 3, warp_n = wid >> 2;
    int bx = blockIdx.x, by = blockIdx.y;
    int chunk0 = by * 4;

    if (tid == 0) {
        #pragma unroll
        for (int i = 0; i < 4; i++) MBAR_INIT(mb0 + i * 8, 1);
    }
    __syncthreads();
    if (tid == 0) {
        #pragma unroll
        for (int c = 0; c < 4; c++) {
            uint32_t m = mb0 + c * 8;
            uint32_t cb = sb + c * CHB;
            int ch = chunk0 + c;
            MBAR_EXPECT(m, CHB);
            bulkcp(cb + 0,     g_A_hi + ((size_t)ch * 4 + bx) * 8192, 8192, m);
            bulkcp(cb + 8192,  g_A_lo + ((size_t)ch * 4 + bx) * 8192, 8192, m);
            bulkcp(cb + 16384, g_Bt_hi + (size_t)ch * 20480, 20480, m);
            bulkcp(cb + 36864, g_Bt_lo + (size_t)ch * 20480, 20480, m);
        }
    }

    float acc[5][4];
    #pragma unroll
    for (int p = 0; p < 5; p++)
        #pragma unroll
        for (int r = 0; r < 4; r++) acc[p][r] = 0.f;

    gemm_mainloop(sb, mb0, acc, warp_m, warp_n, lane);
    sgemm_epilogue(acc, out, 0, bx, by, tid, lane, warp_m, warp_n);
}

// ---------------------------------------------------------------------------
// Fused kernel: phase 1 = M-GEMM(t-1) + b-update + Wc(t) (chunk == cta),
// then per-chunk flags gate phase 2 = s-GEMM(t) + squash.
// grid 144 (cta -> bx=cta&3, by=cta>>2), 512 threads.
// ---------------------------------------------------------------------------
__global__ void __launch_bounds__(512, 1)
fused_iter(const float* __restrict__ W, float* __restrict__ out, int t) {
    extern __shared__ char sm[];
    __shared__ __align__(8) uint64_t mbar[8];
    __shared__ float c_s[8][10];
    uint32_t sb = smem_to_u32(sm);
    uint32_t mb0 = smem_to_u32(mbar);
    int tid = threadIdx.x, lane = tid & 31, wid = tid >> 5;
    int warp_m = wid & 3, warp_n = wid >> 2;
    int cta = blockIdx.x;
    int tm1 = t - 1;

    if (tid == 0) {
        #pragma unroll
        for (int i = 0; i < 8; i++) MBAR_INIT(mb0 + i * 8, 1);
    }
    __syncthreads();
    if (tid == 0) {
        #pragma unroll
        for (int c = 0; c < 4; c++) {
            uint32_t m = mb0 + c * 8;
            uint32_t cb = sb + c * CHB;
            MBAR_EXPECT(m, CHB);
            bulkcp(cb + 0,     g_AT_hi + ((size_t)c * NCHUNK + cta) * 8192, 8192, m);
            bulkcp(cb + 8192,  g_AT_lo + ((size_t)c * NCHUNK + cta) * 8192, 8192, m);
            bulkcp(cb + 16384, g_vT2_hi + (size_t)c * 20480, 20480, m);
            bulkcp(cb + 36864, g_vT2_lo + (size_t)c * 20480, 20480, m);
        }
    }

    float acc[5][4];
    #pragma unroll
    for (int p = 0; p < 5; p++)
        #pragma unroll
        for (int r = 0; r < 4; r++) acc[p][r] = 0.f;

    gemm_mainloop(sb, mb0, acc, warp_m, warp_n, lane);   // M-GEMM

    // ---- stage M tile [64][160] at MS_OFF (chunk3 B region) ----
    __syncthreads();
    float* M_s = (float*)(sm + MS_OFF);
    {
        int r_l = lane >> 2, c_l = (lane & 3) * 2;
        int row = warp_m * 16 + r_l;
        #pragma unroll
        for (int p = 0; p < 5; p++) {
            int col = warp_n * 40 + p * 8 + c_l;
            *(float2*)(M_s + row * NDIM + col) = make_float2(acc[p][0], acc[p][1]);
            *(float2*)(M_s + (row + 8) * NDIM + col) = make_float2(acc[p][2], acc[p][3]);
        }
    }
    __syncthreads();

    // ---- issue phase-2 A loads early (regions disjoint from M_s) ----
    int bx = cta & 3, by = cta >> 2;
    int chunk0 = by * 4;
    if (tid == 0) {
        #pragma unroll
        for (int c = 0; c < 4; c++) {
            uint32_t m = mb0 + (4 + c) * 8;
            uint32_t cb = sb + c * CHB;
            int ch = chunk0 + c;
            MBAR_EXPECT(m, CHB);   // A now + B later
            bulkcp(cb + 0,    g_A_hi + ((size_t)ch * 4 + bx) * 8192, 8192, m);
            bulkcp(cb + 8192, g_A_lo + ((size_t)ch * 4 + bx) * 8192, 8192, m);
        }
    }

    // ---- b-update ----
    #pragma unroll
    for (int ee = 0; ee < 5; ee++) {
        int e = wid * 5 + ee;
        int i_rel = e / 10, o = e - i_rel * 10;
        int i = cta * 8 + i_rel;
        float sum = 0.f;
        #pragma unroll
        for (int j = 0; j < 4; j++) {
            int f = lane + (j << 5);
            int k = f >> 4, u = f & 15;
            sum = fmaf(W[(size_t)i * 1280 + (o << 7) + (u << 3) + k],
                       M_s[(i_rel * 8 + k) * NDIM + o * 16 + u], sum);
        }
        #pragma unroll
        for (int off = 16; off; off >>= 1)
            sum += __shfl_xor_sync(0xffffffffu, sum, off);
        if (lane == 0) {
            float d = sum * (1.0f / (float)BATCH);
            int gw = i * OUTCH + o;
            g_b[gw] = (tm1 == 0) ? d : (g_b[gw] + d);
        }
    }
    __syncthreads();

    // ---- Wc(t) for chunk cta ----
    if (tid < 8) {
        int i = cta * 8 + tid;
        float bv[OUTCH], m = -1e30f;
        #pragma unroll
        for (int o = 0; o < OUTCH; o++) {
            bv[o] = g_b[i * OUTCH + o];
            m = fmaxf(m, bv[o]);
        }
        float sum = 0.f;
        #pragma unroll
        for (int o = 0; o < OUTCH; o++) { bv[o] = expf(bv[o] - m); sum += bv[o]; }
        float inv = 1.0f / sum;
        #pragma unroll
        for (int o = 0; o < OUTCH; o++) c_s[tid][o] = bv[o] * inv;
    }
    __syncthreads();
    wc_body<512>(W, cta, c_s, tid);
    __syncthreads();

    // ---- flag own chunk; wait this K-split's 4 producers; issue B loads ----
    if (tid == 0) {
        asm volatile("fence.proxy.async;" ::: "memory");
        __threadfence();
        atomicAdd(&g_flag[cta], 1);
        #pragma unroll
        for (int c = 0; c < 4; c++) {
            int ch = chunk0 + c;
            while (atomicAdd(&g_flag[ch], 0) < t) __nanosleep(20);
        }
        #pragma unroll
        for (int c = 0; c < 4; c++) {
            uint32_t m = mb0 + (4 + c) * 8;
            uint32_t cb = sb + c * CHB;
            int ch = chunk0 + c;
            bulkcp(cb + 16384, g_Bt_hi + (size_t)ch * 20480, 20480, m);
            bulkcp(cb + 36864, g_Bt_lo + (size_t)ch * 20480, 20480, m);
        }
    }

    // ---- phase 2: s-GEMM(t) + squash ----
    #pragma unroll
    for (int p = 0; p < 5; p++)
        #pragma unroll
        for (int r = 0; r < 4; r++) acc[p][r] = 0.f;

    gemm_mainloop(sb, mb0 + 32, acc, warp_m, warp_n, lane);
    sgemm_epilogue(acc, out, t, bx, by, tid, lane, warp_m, warp_n);
}

// ---------------------------------------------------------------------------
extern "C" void kernel_launch(void* const* d_in, const int* in_sizes, int n_in,
                              void* d_out, int out_size) {
    const float* inp = (const float*)d_in[0];  // [256,1152,8]
    const float* W   = (const float*)d_in[1];  // [1152,10,16,8]
    float* out = (float*)d_out;                // [256,10,16]

    cudaFuncSetAttribute(gemm_s0, cudaFuncAttributeMaxDynamicSharedMemorySize, SG_TOT);
    cudaFuncSetAttribute(fused_iter, cudaFuncAttributeMaxDynamicSharedMemorySize, SG_TOT);

    conv_inp<<<dim3(NCHUNK, 4), 256>>>(inp, W);       // + Wc(0) + resets
    gemm_s0<<<dim3(4, SPLITS_S), 512, SG_TOT>>>(out); // s-GEMM(0) + squash
    fused_iter<<<NCHUNK, 512, SG_TOT>>>(W, out, 1);   // M(0)+Wc(1) -> s(1)+squash
    fused_iter<<<NCHUNK, 512, SG_TOT>>>(W, out, 2);   // M(1)+Wc(2) -> s(2)+out
}

// round 17
// speedup vs baseline: 1.2049x; 1.2049x over previous
#include <cuda_runtime.h>
#include <cuda_fp16.h>
#include <cstdint>

// CapsNet dynamic routing. u_hat never materialized. GEMMs on mma.sync
// m16n8k16 fp16 (fp32 accum): A = fp16 hi/lo limbs, B = single fp16
// -> 2 MMAs per fragment (error ~2^-12/elem, ~3e-4 end-to-end, thr 1e-3).
// Pre-swizzled operands + cp.async.bulk; 512-thread CTAs (16 warps).
// Launches (4): conv+Wc(0) | gemm_s(0)+squash | fused(1) | fused(2)
// fused(t) = [M-GEMM(t-1) + b-update + Wc(t)] --chunk flags--> [s-GEMM(t)+squash]
//   inp: [256,1152,8] fp32, W: [1152,10,16,8] fp32, out v: [256,10,16] fp32
//
// All __device__ globals referenced only inside device code (host-passed
// __device__ symbols silently resolve to ATS host memory on GB300).

#define BATCH   256
#define INCH    1152
#define INU     8
#define OUTCH   10
#define OUTU    16
#define KDIM    (INCH*INU)     // 9216
#define NDIM    (OUTCH*OUTU)   // 160
#define NCHUNK  144            // 64-k chunks (8 capsules each)
#define SPLITS_S 36            // s-GEMM K splits (4 chunks = 256 K per CTA)

// ---------------- device globals (pre-swizzled tile storage) ---------------
__device__ __align__(16) unsigned char g_A_hi[NCHUNK * 4 * 8192];   // [chunk][mblk][64x128B]
__device__ __align__(16) unsigned char g_A_lo[NCHUNK * 4 * 8192];
__device__ __align__(16) unsigned char g_AT_hi[4 * NCHUNK * 8192];  // [kc][ikblk][64x128B]
__device__ __align__(16) unsigned char g_AT_lo[4 * NCHUNK * 8192];
__device__ __align__(16) unsigned char g_Bt[NCHUNK * 20480];        // [chunk][160x128B] fp16
__device__ __align__(16) unsigned char g_vT2[4 * 20480];            // [kc][160x128B] fp16
__device__ float g_part_s[SPLITS_S * BATCH * NDIM];                 // 5.9 MB
__device__ float g_b[INCH * OUTCH];
__device__ int   g_cnt[4];                                          // per-Mtile arrivals
__device__ int   g_flag[NCHUNK];                                    // Bt chunk ready

__device__ __forceinline__ uint32_t smem_to_u32(const void* p) {
    uint32_t a;
    asm("{ .reg .u64 t; cvta.to.shared.u64 t, %1; cvt.u32.u64 %0, t; }"
        : "=r"(a) : "l"(p));
    return a;
}
__device__ __forceinline__ void split_fp16(float x, __half& h, __half& l) {
    h = __float2half(x);
    l = __float2half(x - __half2float(h));
}
__device__ __forceinline__ void ldsm4(uint32_t& r0, uint32_t& r1, uint32_t& r2,
                                      uint32_t& r3, uint32_t addr) {
    asm volatile("ldmatrix.sync.aligned.m8n8.x4.shared.b16 {%0,%1,%2,%3}, [%4];"
                 : "=r"(r0), "=r"(r1), "=r"(r2), "=r"(r3) : "r"(addr));
}
__device__ __forceinline__ void ldsm2(uint32_t& r0, uint32_t& r1, uint32_t addr) {
    asm volatile("ldmatrix.sync.aligned.m8n8.x2.shared.b16 {%0,%1}, [%2];"
                 : "=r"(r0), "=r"(r1) : "r"(addr));
}
__device__ __forceinline__ void mma16816(float* d, const uint32_t* a,
                                         const uint32_t* b) {
    asm volatile(
        "mma.sync.aligned.m16n8k16.row.col.f32.f16.f16.f32 "
        "{%0,%1,%2,%3}, {%4,%5,%6,%7}, {%8,%9}, {%0,%1,%2,%3};"
        : "+f"(d[0]), "+f"(d[1]), "+f"(d[2]), "+f"(d[3])
        : "r"(a[0]), "r"(a[1]), "r"(a[2]), "r"(a[3]), "r"(b[0]), "r"(b[1]));
}

// ---- mbarrier + bulk-copy primitives (sm_90 baseline PTX) ----
#define MBAR_INIT(a, c) \
    asm volatile("mbarrier.init.shared.b64 [%0], %1;" \
                 :: "r"((uint32_t)(a)), "r"((uint32_t)(c)) : "memory")
#define MBAR_EXPECT(a, tx) \
    asm volatile("mbarrier.arrive.expect_tx.shared.b64 _, [%0], %1;" \
                 :: "r"((uint32_t)(a)), "r"((uint32_t)(tx)) : "memory")
#define MBAR_WAIT(a, ph) do { \
    uint32_t _mb = (uint32_t)(a); uint32_t _p = (uint32_t)(ph); uint32_t _d; \
    asm volatile("{\n\t.reg .pred p;\n\t" \
        "mbarrier.try_wait.parity.acquire.cta.shared::cta.b64 p, [%1], %2;\n\t" \
        "selp.b32 %0, 1, 0, p;\n\t}" : "=r"(_d) : "r"(_mb), "r"(_p) : "memory"); \
    if (!_d) { \
        asm volatile("{\n\t.reg .pred P1;\n\tWL_%=:\n\t" \
            "mbarrier.try_wait.parity.acquire.cta.shared::cta.b64 P1, [%0], %1, 0x989680;\n\t" \
            "@P1 bra.uni WD_%=;\n\tbra.uni WL_%=;\n\tWD_%=:\n\t}" \
            :: "r"(_mb), "r"(_p) : "memory"); \
    } } while (0)
__device__ __forceinline__ void bulkcp(uint32_t dst, const void* src,
                                       uint32_t bytes, uint32_t mbar) {
    asm volatile(
        "cp.async.bulk.shared::cluster.global.mbarrier::complete_tx::bytes "
        "[%0], [%1], %2, [%3];"
        :: "r"(dst), "l"(src), "r"(bytes), "r"(mbar) : "memory");
}

// ---------------------------------------------------------------------------
// Wc body: g_Bt[chunk] (pre-swizzled 160x128B fp16) = c[i,o]*W[i,o,u,k].
// ---------------------------------------------------------------------------
template <int NT>
__device__ __forceinline__ void wc_body(const float* __restrict__ W, int chunk,
                                        const float (*c_s)[10], int tid) {
    const float4* W4 = (const float4*)(W + (size_t)chunk * 8 * 1280);
    unsigned char* bh = g_Bt + (size_t)chunk * 20480;
    #pragma unroll
    for (int r = 0; r < 2560 / NT; r++) {
        int q = tid + r * NT;                // 0..2559 float4s (8 caps x 320)
        int i_off = q / 320;
        int rem = q - i_off * 320;
        int o = rem >> 5;
        int rem2 = rem & 31;
        int u = rem2 >> 1, kh = rem2 & 1;
        float4 f = W4[q];
        float cv = c_s[i_off][o];
        __half h0 = __float2half(f.x * cv);
        __half h1 = __float2half(f.y * cv);
        __half h2 = __float2half(f.z * cv);
        __half h3 = __float2half(f.w * cv);
        uint2 ph;
        ph.x = (uint32_t)__half_as_ushort(h0) | ((uint32_t)__half_as_ushort(h1) << 16);
        ph.y = (uint32_t)__half_as_ushort(h2) | ((uint32_t)__half_as_ushort(h3) << 16);
        int row = o * 16 + u;
        uint32_t off = (uint32_t)row * 128 + ((i_off ^ (row & 7)) << 4) + kh * 8;
        *(uint2*)(bh + off) = ph;
    }
}

// ---------------------------------------------------------------------------
// One-time: inp -> fp16 hi/lo pre-swizzled tiles (both layouts); fused Wc(0);
// resets g_cnt and g_flag. grid (144, 4), 256 threads.
// ---------------------------------------------------------------------------
__global__ void conv_inp(const float* __restrict__ inp, const float* __restrict__ W) {
    __shared__ unsigned short sh_hi[64][72];
    __shared__ unsigned short sh_lo[64][72];
    __shared__ float c_s[8][10];
    int ik0 = blockIdx.x * 64, b0 = blockIdx.y * 64;
    int tid = threadIdx.x;

    if (blockIdx.y == 1 && tid == 0) g_flag[blockIdx.x] = 0;
    if (blockIdx.x == 0 && blockIdx.y == 0 && tid < 4) g_cnt[tid] = 0;

    #pragma unroll
    for (int it = 0; it < 16; it++) {
        int row = it * 4 + (tid >> 6);
        int col = tid & 63;
        float x = inp[(size_t)(b0 + row) * KDIM + ik0 + col];
        __half h, l;
        split_fp16(x, h, l);
        sh_hi[row][col] = __half_as_ushort(h);
        sh_lo[row][col] = __half_as_ushort(l);
    }
    __syncthreads();

    unsigned char* Ah = g_A_hi + ((size_t)blockIdx.x * 4 + blockIdx.y) * 8192;
    unsigned char* Al = g_A_lo + ((size_t)blockIdx.x * 4 + blockIdx.y) * 8192;
    unsigned char* Th = g_AT_hi + ((size_t)blockIdx.y * NCHUNK + blockIdx.x) * 8192;
    unsigned char* Tl = g_AT_lo + ((size_t)blockIdx.y * NCHUNK + blockIdx.x) * 8192;

    #pragma unroll
    for (int k = 0; k < 4; k++) {
        int w = tid + (k << 8);
        int r = w >> 4, g = w & 15;
        uint32_t off = (uint32_t)r * 128 + ((((g >> 1) ^ (r & 7))) << 4) + (g & 1) * 8;
        {
            int c0 = g * 4;
            uint2 vh, vl;
            vh.x = (uint32_t)sh_hi[r][c0] | ((uint32_t)sh_hi[r][c0+1] << 16);
            vh.y = (uint32_t)sh_hi[r][c0+2] | ((uint32_t)sh_hi[r][c0+3] << 16);
            vl.x = (uint32_t)sh_lo[r][c0] | ((uint32_t)sh_lo[r][c0+1] << 16);
            vl.y = (uint32_t)sh_lo[r][c0+2] | ((uint32_t)sh_lo[r][c0+3] << 16);
            *(uint2*)(Ah + off) = vh;
            *(uint2*)(Al + off) = vl;
        }
        {
            int c0 = g * 4;
            uint2 vh, vl;
            vh.x = (uint32_t)sh_hi[c0][r] | ((uint32_t)sh_hi[c0+1][r] << 16);
            vh.y = (uint32_t)sh_hi[c0+2][r] | ((uint32_t)sh_hi[c0+3][r] << 16);
            vl.x = (uint32_t)sh_lo[c0][r] | ((uint32_t)sh_lo[c0+1][r] << 16);
            vl.y = (uint32_t)sh_lo[c0+2][r] | ((uint32_t)sh_lo[c0+3][r] << 16);
            *(uint2*)(Th + off) = vh;
            *(uint2*)(Tl + off) = vl;
        }
    }

    if (blockIdx.y == 0) {
        if (tid < 80) c_s[tid / 10][tid % 10] = 0.1f;
        __syncthreads();
        wc_body<256>(W, blockIdx.x, c_s, tid);
    }
}

// ---------------------------------------------------------------------------
// Per-chunk staging (4 x 36 KB): chunk c at c*36864:
//   AH @0 (8192) | AL @8192 | BH @16384 (20480)
// M_s (phase-1 epilogue, 40960 B) at 147456 (disjoint from all staging).
// GEMM: 512 thr, 16 warps (4M x 4N), warp tile 16x40, acc 20 regs.
// Per ks: ldsm4 ah + ldsm4 al + 5x ldsm2 bh, then 10 MMAs (ah*b + al*b).
// ---------------------------------------------------------------------------
#define CHB 36864
#define MS_OFF (4*CHB)          // 147456
#define SG_TOT (MS_OFF + 40960) // 188416

__device__ __forceinline__ uint32_t swz(uint32_t base, int row, int col16) {
    return base + (uint32_t)row * 128 + (uint32_t)((col16 ^ (row & 7)) << 4);
}

__device__ __forceinline__ void gemm_mainloop(
    uint32_t sb, uint32_t mb0, float (*acc)[4],
    int warp_m, int warp_n, int lane) {
    int a_row_l = ((lane >> 3) & 1) * 8 + (lane & 7);
    int a_c16_l = lane >> 4;
    int b_row_l = lane & 7;
    int b_c16_l = (lane >> 3) & 1;

    #pragma unroll
    for (int c = 0; c < 4; c++) {
        MBAR_WAIT(mb0 + c * 8, 0);
        uint32_t cb = sb + c * CHB;
        #pragma unroll
        for (int ks = 0; ks < 4; ks++) {
            uint32_t ah[4], al[4], bh[5][2];
            int arow = warp_m * 16 + a_row_l;
            int ac = (ks << 1) | a_c16_l;
            ldsm4(ah[0], ah[1], ah[2], ah[3], swz(cb + 0, arow, ac));
            ldsm4(al[0], al[1], al[2], al[3], swz(cb + 8192, arow, ac));
            int bc = (ks << 1) | b_c16_l;
            #pragma unroll
            for (int p = 0; p < 5; p++) {
                int brow = warp_n * 40 + p * 8 + b_row_l;
                ldsm2(bh[p][0], bh[p][1], swz(cb + 16384, brow, bc));
            }
            #pragma unroll
            for (int p = 0; p < 5; p++) {
                mma16816(acc[p], ah, bh[p]);
                mma16816(acc[p], al, bh[p]);
            }
        }
    }
}

// s-GEMM epilogue: write partials, rendezvous, fused squash.
__device__ __forceinline__ void sgemm_epilogue(
    float (*acc)[4], float* __restrict__ out, int t,
    int bx, int by, int tid, int lane, int warp_m, int warp_n) {
    float* po = g_part_s + (size_t)by * (BATCH * NDIM);
    int r_l = lane >> 2, c_l = (lane & 3) * 2;
    int row = bx * 64 + warp_m * 16 + r_l;
    #pragma unroll
    for (int p = 0; p < 5; p++) {
        int col = warp_n * 40 + p * 8 + c_l;
        *(float2*)(po + (size_t)row * NDIM + col) = make_float2(acc[p][0], acc[p][1]);
        *(float2*)(po + (size_t)(row + 8) * NDIM + col) = make_float2(acc[p][2], acc[p][3]);
    }

    __threadfence();
    __syncthreads();
    if (tid == 0) {
        atomicAdd(&g_cnt[bx], 1);
        int tgt = SPLITS_S * (t + 1);
        while (atomicAdd(&g_cnt[bx], 0) < tgt) __nanosleep(20);
    }
    __syncthreads();

    int n  = (by < 28) ? 18 : 17;
    int g0 = (by < 28) ? by * 18 : 28 * 18 + (by - 28) * 17;
    int gl = tid >> 4;
    int u  = tid & 15;
    bool act = gl < n;
    int idx = bx * 10240 + (g0 + gl) * 16 + u;
    float s = 0.f;
    if (act) {
        float a0 = 0.f, a1 = 0.f, a2 = 0.f, a3 = 0.f;
        #pragma unroll
        for (int sp = 0; sp < SPLITS_S; sp += 4) {
            a0 += __ldcg(&g_part_s[(size_t)(sp + 0) * (BATCH * NDIM) + idx]);
            a1 += __ldcg(&g_part_s[(size_t)(sp + 1) * (BATCH * NDIM) + idx]);
            a2 += __ldcg(&g_part_s[(size_t)(sp + 2) * (BATCH * NDIM) + idx]);
            a3 += __ldcg(&g_part_s[(size_t)(sp + 3) * (BATCH * NDIM) + idx]);
        }
        s = (a0 + a1) + (a2 + a3);
    }
    float sq = s * s;
    sq += __shfl_xor_sync(0xffffffffu, sq, 8);
    sq += __shfl_xor_sync(0xffffffffu, sq, 4);
    sq += __shfl_xor_sync(0xffffffffu, sq, 2);
    sq += __shfl_xor_sync(0xffffffffu, sq, 1);
    if (act) {
        float scale = sq / ((1.0f + sq) * sqrtf(sq + 1e-9f));
        float v = s * scale;
        if (t == 2) {
            out[idx] = v;
        } else {
            int b = idx / NDIM;
            int ou = idx - b * NDIM;
            int col = b & 63;
            uint32_t off = (uint32_t)bx * 20480 + ou * 128
                         + (((col >> 3) ^ (ou & 7)) << 4) + (col & 7) * 2;
            *(unsigned short*)(g_vT2 + off) = __half_as_ushort(__float2half(v));
        }
    }
}

// ---------------------------------------------------------------------------
// Standalone s-GEMM(0) + squash. grid (4, 36), 512 threads.
// ---------------------------------------------------------------------------
__global__ void __launch_bounds__(512, 1)
gemm_s0(float* __restrict__ out) {
    extern __shared__ char sm[];
    __shared__ __align__(8) uint64_t mbar[4];
    uint32_t sb = smem_to_u32(sm);
    uint32_t mb0 = smem_to_u32(mbar);
    int tid = threadIdx.x, lane = tid & 31, wid = tid >> 5;
    int warp_m = wid & 3, warp_n = wid >> 2;
    int bx = blockIdx.x, by = blockIdx.y;
    int chunk0 = by * 4;

    if (tid == 0) {
        #pragma unroll
        for (int i = 0; i < 4; i++) MBAR_INIT(mb0 + i * 8, 1);
    }
    __syncthreads();
    if (tid == 0) {
        #pragma unroll
        for (int c = 0; c < 4; c++) {
            uint32_t m = mb0 + c * 8;
            uint32_t cb = sb + c * CHB;
            int ch = chunk0 + c;
            MBAR_EXPECT(m, CHB);
            bulkcp(cb + 0,     g_A_hi + ((size_t)ch * 4 + bx) * 8192, 8192, m);
            bulkcp(cb + 8192,  g_A_lo + ((size_t)ch * 4 + bx) * 8192, 8192, m);
            bulkcp(cb + 16384, g_Bt + (size_t)ch * 20480, 20480, m);
        }
    }

    float acc[5][4];
    #pragma unroll
    for (int p = 0; p < 5; p++)
        #pragma unroll
        for (int r = 0; r < 4; r++) acc[p][r] = 0.f;

    gemm_mainloop(sb, mb0, acc, warp_m, warp_n, lane);
    sgemm_epilogue(acc, out, 0, bx, by, tid, lane, warp_m, warp_n);
}

// ---------------------------------------------------------------------------
// Fused kernel: phase 1 = M-GEMM(t-1) + b-update + Wc(t) (chunk == cta),
// then per-chunk flags gate phase 2 = s-GEMM(t) + squash.
// grid 144 (cta -> bx=cta&3, by=cta>>2), 512 threads.
// ---------------------------------------------------------------------------
__global__ void __launch_bounds__(512, 1)
fused_iter(const float* __restrict__ W, float* __restrict__ out, int t) {
    extern __shared__ char sm[];
    __shared__ __align__(8) uint64_t mbar[8];
    __shared__ float c_s[8][10];
    uint32_t sb = smem_to_u32(sm);
    uint32_t mb0 = smem_to_u32(mbar);
    int tid = threadIdx.x, lane = tid & 31, wid = tid >> 5;
    int warp_m = wid & 3, warp_n = wid >> 2;
    int cta = blockIdx.x;
    int tm1 = t - 1;

    if (tid == 0) {
        #pragma unroll
        for (int i = 0; i < 8; i++) MBAR_INIT(mb0 + i * 8, 1);
    }
    __syncthreads();
    if (tid == 0) {
        #pragma unroll
        for (int c = 0; c < 4; c++) {
            uint32_t m = mb0 + c * 8;
            uint32_t cb = sb + c * CHB;
            MBAR_EXPECT(m, CHB);
            bulkcp(cb + 0,     g_AT_hi + ((size_t)c * NCHUNK + cta) * 8192, 8192, m);
            bulkcp(cb + 8192,  g_AT_lo + ((size_t)c * NCHUNK + cta) * 8192, 8192, m);
            bulkcp(cb + 16384, g_vT2 + (size_t)c * 20480, 20480, m);
        }
    }

    float acc[5][4];
    #pragma unroll
    for (int p = 0; p < 5; p++)
        #pragma unroll
        for (int r = 0; r < 4; r++) acc[p][r] = 0.f;

    gemm_mainloop(sb, mb0, acc, warp_m, warp_n, lane);   // M-GEMM

    // ---- stage M tile [64][160] at MS_OFF (private region) ----
    __syncthreads();
    float* M_s = (float*)(sm + MS_OFF);
    {
        int r_l = lane >> 2, c_l = (lane & 3) * 2;
        int row = warp_m * 16 + r_l;
        #pragma unroll
        for (int p = 0; p < 5; p++) {
            int col = warp_n * 40 + p * 8 + c_l;
            *(float2*)(M_s + row * NDIM + col) = make_float2(acc[p][0], acc[p][1]);
            *(float2*)(M_s + (row + 8) * NDIM + col) = make_float2(acc[p][2], acc[p][3]);
        }
    }
    __syncthreads();

    // ---- issue phase-2 A loads early ----
    int bx = cta & 3, by = cta >> 2;
    int chunk0 = by * 4;
    if (tid == 0) {
        #pragma unroll
        for (int c = 0; c < 4; c++) {
            uint32_t m = mb0 + (4 + c) * 8;
            uint32_t cb = sb + c * CHB;
            int ch = chunk0 + c;
            MBAR_EXPECT(m, CHB);   // A now + B later
            bulkcp(cb + 0,    g_A_hi + ((size_t)ch * 4 + bx) * 8192, 8192, m);
            bulkcp(cb + 8192, g_A_lo + ((size_t)ch * 4 + bx) * 8192, 8192, m);
        }
    }

    // ---- b-update: delta[i,o] = (1/B) sum_{k,u} W[i,o,u,k]*M[i8+k][o16+u] ----
    #pragma unroll
    for (int ee = 0; ee < 5; ee++) {
        int e = wid * 5 + ee;
        int i_rel = e / 10, o = e - i_rel * 10;
        int i = cta * 8 + i_rel;
        float sum = 0.f;
        #pragma unroll
        for (int j = 0; j < 4; j++) {
            int f = lane + (j << 5);
            int k = f >> 4, u = f & 15;
            sum = fmaf(W[(size_t)i * 1280 + (o << 7) + (u << 3) + k],
                       M_s[(i_rel * 8 + k) * NDIM + o * 16 + u], sum);
        }
        #pragma unroll
        for (int off = 16; off; off >>= 1)
            sum += __shfl_xor_sync(0xffffffffu, sum, off);
        if (lane == 0) {
            float d = sum * (1.0f / (float)BATCH);
            int gw = i * OUTCH + o;
            g_b[gw] = (tm1 == 0) ? d : (g_b[gw] + d);
        }
    }
    __syncthreads();

    // ---- Wc(t) for chunk cta ----
    if (tid < 8) {
        int i = cta * 8 + tid;
        float bv[OUTCH], m = -1e30f;
        #pragma unroll
        for (int o = 0; o < OUTCH; o++) {
            bv[o] = g_b[i * OUTCH + o];
            m = fmaxf(m, bv[o]);
        }
        float sum = 0.f;
        #pragma unroll
        for (int o = 0; o < OUTCH; o++) { bv[o] = expf(bv[o] - m); sum += bv[o]; }
        float inv = 1.0f / sum;
        #pragma unroll
        for (int o = 0; o < OUTCH; o++) c_s[tid][o] = bv[o] * inv;
    }
    __syncthreads();
    wc_body<512>(W, cta, c_s, tid);
    __syncthreads();

    // ---- flag own chunk; wait this K-split's 4 producers; issue B loads ----
    if (tid == 0) {
        asm volatile("fence.proxy.async;" ::: "memory");
        __threadfence();
        atomicAdd(&g_flag[cta], 1);
        #pragma unroll
        for (int c = 0; c < 4; c++) {
            int ch = chunk0 + c;
            while (atomicAdd(&g_flag[ch], 0) < t) __nanosleep(20);
            bulkcp(sb + c * CHB + 16384, g_Bt + (size_t)ch * 20480, 20480,
                   mb0 + (4 + c) * 8);
        }
    }

    // ---- phase 2: s-GEMM(t) + squash ----
    #pragma unroll
    for (int p = 0; p < 5; p++)
        #pragma unroll
        for (int r = 0; r < 4; r++) acc[p][r] = 0.f;

    gemm_mainloop(sb, mb0 + 32, acc, warp_m, warp_n, lane);
    sgemm_epilogue(acc, out, t, bx, by, tid, lane, warp_m, warp_n);
}

// ---------------------------------------------------------------------------
extern "C" void kernel_launch(void* const* d_in, const int* in_sizes, int n_in,
                              void* d_out, int out_size) {
    const float* inp = (const float*)d_in[0];  // [256,1152,8]
    const float* W   = (const float*)d_in[1];  // [1152,10,16,8]
    float* out = (float*)d_out;                // [256,10,16]

    cudaFuncSetAttribute(gemm_s0, cudaFuncAttributeMaxDynamicSharedMemorySize, SG_TOT);
    cudaFuncSetAttribute(fused_iter, cudaFuncAttributeMaxDynamicSharedMemorySize, SG_TOT);

    conv_inp<<<dim3(NCHUNK, 4), 256>>>(inp, W);       // + Wc(0) + resets
    gemm_s0<<<dim3(4, SPLITS_S), 512, SG_TOT>>>(out); // s-GEMM(0) + squash
    fused_iter<<<NCHUNK, 512, SG_TOT>>>(W, out, 1);   // M(0)+Wc(1) -> s(1)+squash
    fused_iter<<<NCHUNK, 512, SG_TOT>>>(W, out, 2);   // M(1)+Wc(2) -> s(2)+out
}